// round 10
// baseline (speedup 1.0000x reference)
#include <cuda_runtime.h>
#include <cuda_fp16.h>
#include <cuda_bf16.h>
#include <cstdint>

#define OUT_F 8192
#define IN_F  8192
#define TOKENS 256
#define KPAD  8256          // 8192 + 16 lora cols + 48 zero pad
#define NITER 129           // KPAD / 64

// Scratch (device globals — no cudaMalloc allowed)
__device__ __half g_Wx[(size_t)OUT_F * KPAD];   // dequantized W | lora_b | zeros (fp16)
__device__ __half g_xh[(size_t)TOKENS * KPAD];  // x fp16 | t1 fp16 | zeros
__device__ int g_wn_mode;                       // 0=f32, 1=f16, 2=bf16

__device__ __forceinline__ uint32_t smem_u32(const void* p) {
    uint32_t a;
    asm("{ .reg .u64 t; cvta.to.shared.u64 t, %1; cvt.u32.u64 %0, t; }" : "=r"(a) : "l"(p));
    return a;
}

// ---------------- fused prep: xconv + t1 + wn-dtype probe ----------------
#define XC_BLOCKS 1030
#define T1_BLOCKS 32
#define PREP_BLOCKS (XC_BLOCKS + T1_BLOCKS + 1)

__global__ void __launch_bounds__(256) qlora_prep(const float* __restrict__ x,
                                                  const float* __restrict__ la,
                                                  const void* __restrict__ wn) {
    const int blk = blockIdx.x;
    if (blk < XC_BLOCKS) {
        int tid = blk * 256 + threadIdx.x;
        const int MAIN = TOKENS * IN_F / 8;  // 262144
        if (tid < MAIN) {
            int e = tid << 3;
            int t = e >> 13, i = e & 8191;
            float4 f0 = *(const float4*)(x + e);
            float4 f1 = *(const float4*)(x + e + 4);
            __half2 h0 = __floats2half2_rn(f0.x, f0.y);
            __half2 h1 = __floats2half2_rn(f0.z, f0.w);
            __half2 h2 = __floats2half2_rn(f1.x, f1.y);
            __half2 h3 = __floats2half2_rn(f1.z, f1.w);
            uint4 v;
            v.x = *(uint32_t*)&h0; v.y = *(uint32_t*)&h1;
            v.z = *(uint32_t*)&h2; v.w = *(uint32_t*)&h3;
            *(uint4*)(g_xh + (size_t)t * KPAD + i) = v;
        } else {
            int p = tid - MAIN;
            if (p < TOKENS * 6) {
                int t = p / 6, u = p % 6;
                uint4 z = {0u, 0u, 0u, 0u};
                *(uint4*)(g_xh + (size_t)t * KPAD + 8208 + u * 8) = z;
            }
        }
    } else if (blk < XC_BLOCKS + T1_BLOCKS) {
        int t = (blk - XC_BLOCKS) * 8 + (threadIdx.x >> 5);
        int lid = threadIdx.x & 31;
        float acc[16];
#pragma unroll
        for (int r = 0; r < 16; r++) acc[r] = 0.f;
        for (int i = 0; i < 64; i++) {
            int k = i * 128 + lid * 4;
            float4 xv = *(const float4*)(x + (size_t)t * IN_F + k);
#pragma unroll
            for (int r = 0; r < 16; r++) {
                float4 av = __ldg((const float4*)(la + (size_t)r * IN_F + k));
                acc[r] += xv.x * av.x + xv.y * av.y + xv.z * av.z + xv.w * av.w;
            }
        }
#pragma unroll
        for (int r = 0; r < 16; r++) {
            float v = acc[r];
#pragma unroll
            for (int s = 16; s; s >>= 1) v += __shfl_xor_sync(0xFFFFFFFFu, v, s);
            if (lid == r) g_xh[(size_t)t * KPAD + 8192 + r] = __float2half_rn(v);
        }
    } else if (threadIdx.x == 0) {
        const uint32_t* w32 = (const uint32_t*)wn;
        int cf = 0;
        for (int i = 0; i < 128; i++) {
            float f = __uint_as_float(w32[i]);
            if (f > 0.004f && f < 1.05f) cf++;
        }
        if (cf >= 100) { g_wn_mode = 0; return; }
        const uint16_t* w16 = (const uint16_t*)wn;
        int ch = 0;
        for (int i = 0; i < 256; i++) if (w16[i] < 0x3C08u) ch++;
        g_wn_mode = (ch >= 128) ? 1 : 2;
    }
}

// ---------------- dequant (R8-proven) ----------------
__device__ __forceinline__ void cvt4(int wv, float a, float n, uint32_t& p0, uint32_t& p1) {
    float v0 = fmaf((float)(wv & 3), a, -n);
    float v1 = fmaf((float)((wv >> 2) & 3), a, -n);
    float v2 = fmaf((float)((wv >> 4) & 3), a, -n);
    float v3 = fmaf((float)((wv >> 6) & 3), a, -n);
    __half2 h0 = __floats2half2_rn(v0, v1);
    __half2 h1 = __floats2half2_rn(v2, v3);
    p0 = *(uint32_t*)&h0;
    p1 = *(uint32_t*)&h1;
}

__global__ void __launch_bounds__(256) qlora_dequant(const int* __restrict__ q2,
                                                     const void* __restrict__ wn,
                                                     const float* __restrict__ lb) {
    const int tid = blockIdx.x * 256 + threadIdx.x;
    const int MAIN = (OUT_F * IN_F / 4) / 4;  // 4,194,304
    if (tid < MAIN) {
        const int idx32 = tid << 2;
        const int4 w = *(const int4*)(q2 + idx32);
        const int g = idx32 >> 5;
        const int mode = g_wn_mode;
        float n;
        if (mode == 0)      n = ((const float*)wn)[g];
        else if (mode == 1) n = __half2float(((const __half*)wn)[g]);
        else                n = __bfloat162float(((const __nv_bfloat16*)wn)[g]);
        const float a = n * (2.0f / 3.0f);
        const int o = g >> 6;
        const int i = ((g & 63) << 7) | ((idx32 & 31) << 2);
        __half* dst = g_Wx + (size_t)o * KPAD + i;
        uint4 s0, s1;
        cvt4(w.x, a, n, s0.x, s0.y);
        cvt4(w.y, a, n, s0.z, s0.w);
        cvt4(w.z, a, n, s1.x, s1.y);
        cvt4(w.w, a, n, s1.z, s1.w);
        *(uint4*)dst = s0;
        *(uint4*)(dst + 8) = s1;
    } else {
        int p = tid - MAIN;
        if (p < OUT_F * 8) {
            int o = p >> 3, u = p & 7;
            uint4 v = {0u, 0u, 0u, 0u};
            if (u < 2) {
                const float* s = lb + (size_t)o * 16 + u * 8;
                __half2 h0 = __floats2half2_rn(s[0], s[1]);
                __half2 h1 = __floats2half2_rn(s[2], s[3]);
                __half2 h2 = __floats2half2_rn(s[4], s[5]);
                __half2 h3 = __floats2half2_rn(s[6], s[7]);
                v.x = *(uint32_t*)&h0; v.y = *(uint32_t*)&h1;
                v.z = *(uint32_t*)&h2; v.w = *(uint32_t*)&h3;
            }
            *(uint4*)(g_Wx + (size_t)o * KPAD + 8192 + u * 8) = v;
        }
    }
}

// ---------------- GEMM: mma.sync, CTA tile 128(M) x 64(N) ----------------
// grid (128, 2) = 256 CTAs -> all 148 SMs, 2-3 CTAs/SM (occupancy fix).
// 8 warps, warp grid 4(M) x 2(N), warp tile 32x32 -> acc = 32 regs.
// Double-buffered cp.async; padded 72-half rows (conflict-free, no swizzle).
#define ROWP 72
#define ATILE_B (128 * ROWP * 2)     // 18432
#define BTILE_B (64 * ROWP * 2)      // 9216
#define STG_B (ATILE_B + BTILE_B)    // 27648
#define GEMM_SMEM (2 * STG_B)        // 55296

__device__ __forceinline__ void mma16816(float& c0, float& c1, float& c2, float& c3,
                                         uint32_t a0, uint32_t a1, uint32_t a2, uint32_t a3,
                                         uint32_t b0, uint32_t b1) {
    asm volatile("mma.sync.aligned.m16n8k16.row.col.f32.f16.f16.f32 "
                 "{%0,%1,%2,%3}, {%4,%5,%6,%7}, {%8,%9}, {%0,%1,%2,%3};"
                 : "+f"(c0), "+f"(c1), "+f"(c2), "+f"(c3)
                 : "r"(a0), "r"(a1), "r"(a2), "r"(a3), "r"(b0), "r"(b1));
}

__global__ void __launch_bounds__(256) qlora_gemm(const float* __restrict__ bias,
                                                  float* __restrict__ out) {
    extern __shared__ char smem[];
    const uint32_t sb = smem_u32(smem);
    const int tid = threadIdx.x;
    const int wid = tid >> 5;
    const int lid = tid & 31;
    const int bx = blockIdx.x;       // N tile 0..127 (64 cols each)
    const int by = blockIdx.y;       // M tile 0..1 (128 rows each)
    const int wm = wid & 3;          // 4 M-warps x 32 rows
    const int wn2 = wid >> 2;        // 2 N-warps x 32 cols
    const int fr = lid >> 2;
    const int fc = (lid & 3) << 1;

    const int cr = tid >> 1;         // 0..127
    const int hs = tid & 1;
    const __half* Ag = g_xh + (size_t)(by * 128 + cr) * KPAD;
    const __half* Bg = g_Wx + (size_t)(bx * 64 + (cr & 63)) * KPAD;

    auto issue = [&](int buf, int kk) {
        // A: 128 rows, 2 threads/row (64B each)
        uint32_t aDst = sb + buf * STG_B + cr * (ROWP * 2) + hs * 64;
        const char* aSrc = (const char*)(Ag + kk + hs * 32);
#pragma unroll
        for (int u = 0; u < 4; u++)
            asm volatile("cp.async.cg.shared.global [%0], [%1], 16;"
                         :: "r"(aDst + u * 16), "l"(aSrc + u * 16) : "memory");
        // B: 64 rows, threads 0..127
        if (tid < 128) {
            uint32_t bDst = sb + buf * STG_B + ATILE_B + cr * (ROWP * 2) + hs * 64;
            const char* bSrc = (const char*)(Bg + kk + hs * 32);
#pragma unroll
            for (int u = 0; u < 4; u++)
                asm volatile("cp.async.cg.shared.global [%0], [%1], 16;"
                             :: "r"(bDst + u * 16), "l"(bSrc + u * 16) : "memory");
        }
    };

    float acc[2][4][4];
#pragma unroll
    for (int mi = 0; mi < 2; mi++)
#pragma unroll
        for (int ni = 0; ni < 4; ni++)
#pragma unroll
            for (int r = 0; r < 4; r++) acc[mi][ni][r] = 0.f;

    issue(0, 0);
    asm volatile("cp.async.commit_group;" ::: "memory");

    for (int it = 0; it < NITER; it++) {
        if (it + 1 < NITER) issue((it + 1) & 1, (it + 1) * 64);
        asm volatile("cp.async.commit_group;" ::: "memory");
        asm volatile("cp.async.wait_group 1;" ::: "memory");
        __syncthreads();

        const __half* As = (const __half*)(smem + (it & 1) * STG_B);
        const __half* Bs = (const __half*)(smem + (it & 1) * STG_B + ATILE_B);

#pragma unroll
        for (int ks = 0; ks < 4; ks++) {
            const int kb = ks * 16;
            uint32_t a[2][4];
#pragma unroll
            for (int mi = 0; mi < 2; mi++) {
                const __half* ap = As + (wm * 32 + mi * 16 + fr) * ROWP + kb + fc;
                a[mi][0] = *(const uint32_t*)(ap);
                a[mi][1] = *(const uint32_t*)(ap + 8 * ROWP);
                a[mi][2] = *(const uint32_t*)(ap + 8);
                a[mi][3] = *(const uint32_t*)(ap + 8 * ROWP + 8);
            }
#pragma unroll
            for (int ni = 0; ni < 4; ni++) {
                const __half* bp = Bs + (wn2 * 32 + ni * 8 + fr) * ROWP + kb + fc;
                uint32_t b0 = *(const uint32_t*)(bp);
                uint32_t b1 = *(const uint32_t*)(bp + 8);
#pragma unroll
                for (int mi = 0; mi < 2; mi++)
                    mma16816(acc[mi][ni][0], acc[mi][ni][1], acc[mi][ni][2], acc[mi][ni][3],
                             a[mi][0], a[mi][1], a[mi][2], a[mi][3], b0, b1);
            }
        }
        __syncthreads();
    }
    asm volatile("cp.async.wait_group 0;" ::: "memory");

    // epilogue
    const int m0 = by * 128 + wm * 32 + fr;
    const int n00 = bx * 64 + wn2 * 32 + fc;
#pragma unroll
    for (int mi = 0; mi < 2; mi++) {
#pragma unroll
        for (int ni = 0; ni < 4; ni++) {
            int n = n00 + ni * 8;
            float b0 = __ldg(bias + n), b1 = __ldg(bias + n + 1);
            int mA = m0 + mi * 16;
            float2 v0 = {acc[mi][ni][0] + b0, acc[mi][ni][1] + b1};
            float2 v1 = {acc[mi][ni][2] + b0, acc[mi][ni][3] + b1};
            *(float2*)(out + (size_t)mA * OUT_F + n) = v0;
            *(float2*)(out + (size_t)(mA + 8) * OUT_F + n) = v1;
        }
    }
}

// ---------------- launch ----------------
extern "C" void kernel_launch(void* const* d_in, const int* in_sizes, int n_in,
                              void* d_out, int out_size) {
    int ix = -1, iq = -1, iwn = -1, ib = -1, ila = -1, ilb = -1;
    for (int i = 0; i < n_in; i++) {
        int s = in_sizes[i];
        if (s == TOKENS * IN_F)            ix = i;
        else if (s == OUT_F * IN_F / 4)    iq = i;
        else if (s == OUT_F * IN_F / 128)  iwn = i;
        else if (s == OUT_F)               ib = i;
        else if (s == 16 * IN_F)           { if (ila < 0) ila = i; else ilb = i; }
    }
    const float* x    = (const float*)d_in[ix];
    const int*   q2   = (const int*)d_in[iq];
    const void*  wn   = (const void*)d_in[iwn];
    const float* bias = (const float*)d_in[ib];
    const float* la   = (const float*)d_in[ila];
    const float* lb   = (const float*)d_in[ilb];
    float* out = (float*)d_out;

    qlora_prep<<<PREP_BLOCKS, 256>>>(x, la, wn);
    qlora_dequant<<<(4194304 + 65536) / 256, 256>>>(q2, wn, lb);

    cudaFuncSetAttribute(qlora_gemm, cudaFuncAttributeMaxDynamicSharedMemorySize, GEMM_SMEM);
    qlora_gemm<<<dim3(128, 2), 256, GEMM_SMEM>>>(bias, out);
}

// round 11
// speedup vs baseline: 2.1033x; 2.1033x over previous
#include <cuda_runtime.h>
#include <cuda_fp16.h>
#include <cuda_bf16.h>
#include <cstdint>

#define OUT_F 8192
#define IN_F  8192
#define TOKENS 256
#define KPAD  8256          // 8192 + 16 lora cols + 48 zero pad
#define NITER 129           // KPAD / 64

// Scratch (device globals — no cudaMalloc allowed)
__device__ __half g_xh[(size_t)TOKENS * KPAD];  // x fp16 | t1 fp16 | zeros
__device__ int g_wn_mode;                       // 0=f32, 1=f16, 2=bf16

__device__ __forceinline__ uint32_t smem_u32(const void* p) {
    uint32_t a;
    asm("{ .reg .u64 t; cvta.to.shared.u64 t, %1; cvt.u32.u64 %0, t; }" : "=r"(a) : "l"(p));
    return a;
}

// ---------------- probe: parallel wn-dtype classify (~3 us) ----------------
__global__ void qlora_probe(const void* __restrict__ wn) {
    __shared__ int cnt[2];
    if (threadIdx.x < 2) cnt[threadIdx.x] = 0;
    __syncthreads();
    if (threadIdx.x < 128) {
        float f = __uint_as_float(((const uint32_t*)wn)[threadIdx.x]);
        if (f > 0.004f && f < 1.05f) atomicAdd(&cnt[0], 1);
    }
    {
        uint16_t h = ((const uint16_t*)wn)[threadIdx.x];  // 256 entries
        if (h < 0x3C08u) atomicAdd(&cnt[1], 1);
    }
    __syncthreads();
    if (threadIdx.x == 0) {
        if (cnt[0] >= 100)      g_wn_mode = 0;
        else if (cnt[1] >= 128) g_wn_mode = 1;
        else                    g_wn_mode = 2;
    }
}

// ---------------- prep: xconv + t1 (parallel t1: 2 lora rows / warp) --------
#define XC_BLOCKS 1030
#define T1_BLOCKS 256                       // one block per token
#define PREP_BLOCKS (XC_BLOCKS + T1_BLOCKS)

__global__ void __launch_bounds__(256) qlora_prep(const float* __restrict__ x,
                                                  const float* __restrict__ la) {
    const int blk = blockIdx.x;
    if (blk < XC_BLOCKS) {
        // ---- xconv: x f32 -> g_xh fp16, + zero pad cols [8208,8256) ----
        int tid = blk * 256 + threadIdx.x;
        const int MAIN = TOKENS * IN_F / 8;  // 262144
        if (tid < MAIN) {
            int e = tid << 3;
            int t = e >> 13, i = e & 8191;
            float4 f0 = *(const float4*)(x + e);
            float4 f1 = *(const float4*)(x + e + 4);
            __half2 h0 = __floats2half2_rn(f0.x, f0.y);
            __half2 h1 = __floats2half2_rn(f0.z, f0.w);
            __half2 h2 = __floats2half2_rn(f1.x, f1.y);
            __half2 h3 = __floats2half2_rn(f1.z, f1.w);
            uint4 v;
            v.x = *(uint32_t*)&h0; v.y = *(uint32_t*)&h1;
            v.z = *(uint32_t*)&h2; v.w = *(uint32_t*)&h3;
            *(uint4*)(g_xh + (size_t)t * KPAD + i) = v;
        } else {
            int p = tid - MAIN;
            if (p < TOKENS * 6) {
                int t = p / 6, u = p % 6;
                uint4 z = {0u, 0u, 0u, 0u};
                *(uint4*)(g_xh + (size_t)t * KPAD + 8208 + u * 8) = z;
            }
        }
    } else {
        // ---- t1: token = block; warp w handles lora rows 2w, 2w+1 ----
        const int t = blk - XC_BLOCKS;
        const int w = threadIdx.x >> 5;
        const int lid = threadIdx.x & 31;
        const float* xrow = x + (size_t)t * IN_F;
        const float* a0 = la + (size_t)(2 * w) * IN_F;
        const float* a1 = la + (size_t)(2 * w + 1) * IN_F;
        float s0 = 0.f, s1 = 0.f;
        for (int i = 0; i < 64; i++) {
            int k = i * 128 + lid * 4;
            float4 xv = *(const float4*)(xrow + k);
            float4 v0 = __ldg((const float4*)(a0 + k));
            float4 v1 = __ldg((const float4*)(a1 + k));
            s0 += xv.x * v0.x + xv.y * v0.y + xv.z * v0.z + xv.w * v0.w;
            s1 += xv.x * v1.x + xv.y * v1.y + xv.z * v1.z + xv.w * v1.w;
        }
#pragma unroll
        for (int s = 16; s; s >>= 1) {
            s0 += __shfl_xor_sync(0xFFFFFFFFu, s0, s);
            s1 += __shfl_xor_sync(0xFFFFFFFFu, s1, s);
        }
        if (lid == 0) {
            g_xh[(size_t)t * KPAD + 8192 + 2 * w]     = __float2half_rn(s0);
            g_xh[(size_t)t * KPAD + 8192 + 2 * w + 1] = __float2half_rn(s1);
        }
    }
}

// ---------------- GEMM with fused in-loop 2-bit dequant (R9, 183us) --------
#define ROWP 72
#define TILE_B (128 * ROWP * 2)       // 18432 bytes
#define SM_A 0                        // 3 A buffers
#define SM_B (3 * TILE_B)             // 2 B buffers
#define SM_SEL (SM_B + 2 * TILE_B)    // PRMT selector table
#define GEMM_SMEM (SM_SEL + 1024)     // 93184

__device__ __forceinline__ void mma16816(float& c0, float& c1, float& c2, float& c3,
                                         uint32_t a0, uint32_t a1, uint32_t a2, uint32_t a3,
                                         uint32_t b0, uint32_t b1) {
    asm volatile("mma.sync.aligned.m16n8k16.row.col.f32.f16.f16.f32 "
                 "{%0,%1,%2,%3}, {%4,%5,%6,%7}, {%8,%9}, {%0,%1,%2,%3};"
                 : "+f"(c0), "+f"(c1), "+f"(c2), "+f"(c3)
                 : "r"(a0), "r"(a1), "r"(a2), "r"(a3), "r"(b0), "r"(b1));
}

__device__ __forceinline__ float load_norm(const void* wn, int g, int mode) {
    if (mode == 0) return ((const float*)wn)[g];
    if (mode == 1) return __half2float(((const __half*)wn)[g]);
    return __bfloat162float(((const __nv_bfloat16*)wn)[g]);
}

__global__ void __launch_bounds__(256) qlora_gemm(const int* __restrict__ q2,
                                                  const void* __restrict__ wn,
                                                  const float* __restrict__ lb,
                                                  const float* __restrict__ bias,
                                                  float* __restrict__ out) {
    extern __shared__ char smem[];
    const uint32_t sb = smem_u32(smem);
    const int tid = threadIdx.x;
    const int wid = tid >> 5;
    const int lid = tid & 31;
    const int bx = blockIdx.x;       // N tile 0..63
    const int by = blockIdx.y;       // M tile 0..1
    const int wm = wid & 3;
    const int wn2 = wid >> 2;
    const int fr = lid >> 2;
    const int fc = (lid & 3) << 1;
    const int mode = g_wn_mode;

    uint32_t* selt = (uint32_t*)(smem + SM_SEL);
    {
        int b = tid;
        selt[b] = (uint32_t)((b & 3) | (((b >> 2) & 3) << 4) |
                             (((b >> 4) & 3) << 8) | (((b >> 6) & 3) << 12));
    }

    const int brow = tid >> 1;
    const int hs = tid & 1;
    const int o = bx * 128 + brow;
    const int* crow = q2 + (size_t)o * 2048;

    const __half* Ag = g_xh + (size_t)(by * 128 + brow) * KPAD;
    const uint32_t a_off = (uint32_t)brow * (ROWP * 2) + (uint32_t)hs * 64;

    auto issueA = [&](int buf3, int kk) {
        uint32_t dst = sb + SM_A + buf3 * TILE_B + a_off;
        const char* src = (const char*)(Ag + kk + hs * 32);
#pragma unroll
        for (int u = 0; u < 4; u++)
            asm volatile("cp.async.cg.shared.global [%0], [%1], 16;"
                         :: "r"(dst + u * 16), "l"(src + u * 16) : "memory");
    };

    auto decodeSTS = [&](int j, uint4 C0, uint4 C1, float n) {
        uint32_t r[16];
        if (j < 128) {
            float n3 = n * 0.33333334f;
            __half h0 = __float2half_rn(-n),  h1 = __float2half_rn(-n3);
            __half h2 = __float2half_rn(n3),  h3 = __float2half_rn(n);
            uint32_t p01 = (uint32_t)__half_as_ushort(h0) | ((uint32_t)__half_as_ushort(h1) << 16);
            uint32_t p23 = (uint32_t)__half_as_ushort(h2) | ((uint32_t)__half_as_ushort(h3) << 16);
            uint32_t t_lo = __byte_perm(p01, p23, 0x6420);
            uint32_t t_hi = __byte_perm(p01, p23, 0x7531);
            uint32_t w[8] = {C0.x, C0.y, C0.z, C0.w, C1.x, C1.y, C1.z, C1.w};
#pragma unroll
            for (int i = 0; i < 8; i++) {
                uint32_t sel = selt[w[i] & 0xFF];
                uint32_t lo4 = __byte_perm(t_lo, 0u, sel);
                uint32_t hi4 = __byte_perm(t_hi, 0u, sel);
                r[2 * i]     = __byte_perm(lo4, hi4, 0x5140);
                r[2 * i + 1] = __byte_perm(lo4, hi4, 0x7362);
            }
        } else {
#pragma unroll
            for (int i = 0; i < 16; i++) r[i] = 0u;
            if (hs == 0) {
                r[0] = C0.x; r[1] = C0.y; r[2] = C0.z; r[3] = C0.w;
                r[4] = C1.x; r[5] = C1.y; r[6] = C1.z; r[7] = C1.w;
            }
        }
        char* dst = smem + SM_B + (j & 1) * TILE_B + brow * (ROWP * 2) + hs * 64;
        *(uint4*)(dst)      = make_uint4(r[0], r[1], r[2], r[3]);
        *(uint4*)(dst + 16) = make_uint4(r[4], r[5], r[6], r[7]);
        *(uint4*)(dst + 32) = make_uint4(r[8], r[9], r[10], r[11]);
        *(uint4*)(dst + 48) = make_uint4(r[12], r[13], r[14], r[15]);
    };

    auto loadCodes = [&](int j, uint4& C0, uint4& C1, float& n) {
        if (j < 128) {
            const uint4* p = (const uint4*)(crow + j * 16 + hs * 8);
            C0 = __ldg(p);
            C1 = __ldg(p + 1);
            n = load_norm(wn, o * 64 + (j >> 1), mode);
        } else if (hs == 0) {
            const float4* s = (const float4*)(lb + (size_t)o * 16);
            float4 f0 = __ldg(s), f1 = __ldg(s + 1), f2 = __ldg(s + 2), f3 = __ldg(s + 3);
            __half2 a0 = __floats2half2_rn(f0.x, f0.y), a1 = __floats2half2_rn(f0.z, f0.w);
            __half2 a2 = __floats2half2_rn(f1.x, f1.y), a3 = __floats2half2_rn(f1.z, f1.w);
            __half2 a4 = __floats2half2_rn(f2.x, f2.y), a5 = __floats2half2_rn(f2.z, f2.w);
            __half2 a6 = __floats2half2_rn(f3.x, f3.y), a7 = __floats2half2_rn(f3.z, f3.w);
            C0 = make_uint4(*(uint32_t*)&a0, *(uint32_t*)&a1, *(uint32_t*)&a2, *(uint32_t*)&a3);
            C1 = make_uint4(*(uint32_t*)&a4, *(uint32_t*)&a5, *(uint32_t*)&a6, *(uint32_t*)&a7);
        }
    };

    float acc[2][8][4];
#pragma unroll
    for (int mi = 0; mi < 2; mi++)
#pragma unroll
        for (int ni = 0; ni < 8; ni++)
#pragma unroll
            for (int r = 0; r < 4; r++) acc[mi][ni][r] = 0.f;

    uint4 C0, C1;
    float cn = 0.f;
    loadCodes(0, C0, C1, cn);
    __syncthreads();
    decodeSTS(0, C0, C1, cn);
    issueA(0, 0);  asm volatile("cp.async.commit_group;" ::: "memory");
    issueA(1, 64); asm volatile("cp.async.commit_group;" ::: "memory");
    loadCodes(1, C0, C1, cn);
    __syncthreads();

    int abuf = 0;
    for (int it = 0; it < NITER; it++) {
        asm volatile("cp.async.wait_group 1;" ::: "memory");
        __syncthreads();

        const __half* As = (const __half*)(smem + SM_A + abuf * TILE_B);
        const __half* Bs = (const __half*)(smem + SM_B + (it & 1) * TILE_B);

#pragma unroll
        for (int ks = 0; ks < 2; ks++) {
            const int kb = ks * 16;
            uint32_t a[2][4];
#pragma unroll
            for (int mi = 0; mi < 2; mi++) {
                const __half* ap = As + (wm * 32 + mi * 16 + fr) * ROWP + kb + fc;
                a[mi][0] = *(const uint32_t*)(ap);
                a[mi][1] = *(const uint32_t*)(ap + 8 * ROWP);
                a[mi][2] = *(const uint32_t*)(ap + 8);
                a[mi][3] = *(const uint32_t*)(ap + 8 * ROWP + 8);
            }
#pragma unroll
            for (int ni = 0; ni < 8; ni++) {
                const __half* bp = Bs + (wn2 * 64 + ni * 8 + fr) * ROWP + kb + fc;
                uint32_t b0 = *(const uint32_t*)(bp);
                uint32_t b1 = *(const uint32_t*)(bp + 8);
#pragma unroll
                for (int mi = 0; mi < 2; mi++)
                    mma16816(acc[mi][ni][0], acc[mi][ni][1], acc[mi][ni][2], acc[mi][ni][3],
                             a[mi][0], a[mi][1], a[mi][2], a[mi][3], b0, b1);
            }
        }

        if (it <= 127) decodeSTS(it + 1, C0, C1, cn);
        if (it + 2 <= 128) loadCodes(it + 2, C0, C1, cn);
        if (it + 2 < NITER) {
            int nb = abuf + 2; if (nb >= 3) nb -= 3;
            issueA(nb, (it + 2) * 64);
        }
        asm volatile("cp.async.commit_group;" ::: "memory");

#pragma unroll
        for (int ks = 2; ks < 4; ks++) {
            const int kb = ks * 16;
            uint32_t a[2][4];
#pragma unroll
            for (int mi = 0; mi < 2; mi++) {
                const __half* ap = As + (wm * 32 + mi * 16 + fr) * ROWP + kb + fc;
                a[mi][0] = *(const uint32_t*)(ap);
                a[mi][1] = *(const uint32_t*)(ap + 8 * ROWP);
                a[mi][2] = *(const uint32_t*)(ap + 8);
                a[mi][3] = *(const uint32_t*)(ap + 8 * ROWP + 8);
            }
#pragma unroll
            for (int ni = 0; ni < 8; ni++) {
                const __half* bp = Bs + (wn2 * 64 + ni * 8 + fr) * ROWP + kb + fc;
                uint32_t b0 = *(const uint32_t*)(bp);
                uint32_t b1 = *(const uint32_t*)(bp + 8);
#pragma unroll
                for (int mi = 0; mi < 2; mi++)
                    mma16816(acc[mi][ni][0], acc[mi][ni][1], acc[mi][ni][2], acc[mi][ni][3],
                             a[mi][0], a[mi][1], a[mi][2], a[mi][3], b0, b1);
            }
        }

        abuf++; if (abuf == 3) abuf = 0;
    }
    asm volatile("cp.async.wait_group 0;" ::: "memory");

    const int m0 = by * 128 + wm * 32 + fr;
    const int n00 = bx * 128 + wn2 * 64 + fc;
#pragma unroll
    for (int mi = 0; mi < 2; mi++) {
#pragma unroll
        for (int ni = 0; ni < 8; ni++) {
            int n = n00 + ni * 8;
            float b0 = __ldg(bias + n), b1 = __ldg(bias + n + 1);
            int mA = m0 + mi * 16;
            float2 v0 = {acc[mi][ni][0] + b0, acc[mi][ni][1] + b1};
            float2 v1 = {acc[mi][ni][2] + b0, acc[mi][ni][3] + b1};
            *(float2*)(out + (size_t)mA * OUT_F + n) = v0;
            *(float2*)(out + (size_t)(mA + 8) * OUT_F + n) = v1;
        }
    }
}

// ---------------- launch ----------------
extern "C" void kernel_launch(void* const* d_in, const int* in_sizes, int n_in,
                              void* d_out, int out_size) {
    int ix = -1, iq = -1, iwn = -1, ib = -1, ila = -1, ilb = -1;
    for (int i = 0; i < n_in; i++) {
        int s = in_sizes[i];
        if (s == TOKENS * IN_F)            ix = i;
        else if (s == OUT_F * IN_F / 4)    iq = i;
        else if (s == OUT_F * IN_F / 128)  iwn = i;
        else if (s == OUT_F)               ib = i;
        else if (s == 16 * IN_F)           { if (ila < 0) ila = i; else ilb = i; }
    }
    const float* x    = (const float*)d_in[ix];
    const int*   q2   = (const int*)d_in[iq];
    const void*  wn   = (const void*)d_in[iwn];
    const float* bias = (const float*)d_in[ib];
    const float* la   = (const float*)d_in[ila];
    const float* lb   = (const float*)d_in[ilb];
    float* out = (float*)d_out;

    qlora_probe<<<1, 256>>>(wn);
    qlora_prep<<<PREP_BLOCKS, 256>>>(x, la);

    cudaFuncSetAttribute(qlora_gemm, cudaFuncAttributeMaxDynamicSharedMemorySize, GEMM_SMEM);
    qlora_gemm<<<dim3(64, 2), 256, GEMM_SMEM>>>(q2, wn, lb, bias, out);
}